// round 6
// baseline (speedup 1.0000x reference)
#include <cuda_runtime.h>
#include <cuda_bf16.h>
#include <cstdint>

// Problem constants
#define B_   256
#define V_   50257
#define U_   65536
#define M_   3
#define TJ   16      // j-columns per scatter CTA

// ---------------------------------------------------------------------------
// Scratch (__device__ globals; allocation-free). g_outT is zero-initialized at
// module load; the transpose kernel re-zeroes it after reading so every graph
// replay starts from zeros.
// ---------------------------------------------------------------------------
__device__ float g_outT[(size_t)U_ * B_];   // batch-minor accumulator [u][b], 64MB
__device__ float g_escale[M_ * B_];         // w[m] / rowsum

// ---------------------------------------------------------------------------
// 1) row sums of exp(logits) -> g_escale[m*B+b] = w[m] / sum
// grid: (B, M), block 512. float4 body with alignment head/tail (V is odd).
// ---------------------------------------------------------------------------
__global__ void rowsum_kernel(const float* __restrict__ l0,
                              const float* __restrict__ l1,
                              const float* __restrict__ l2,
                              const float* __restrict__ w) {
    const int b = blockIdx.x;
    const int m = blockIdx.y;
    const float* lg = (m == 0 ? l0 : (m == 1 ? l1 : l2)) + (size_t)b * V_;

    // elements until 16B alignment
    const int head = (int)(((16u - ((uintptr_t)lg & 15u)) & 15u) >> 2);
    const int n4   = (V_ - head) >> 2;
    const int tailstart = head + 4 * n4;

    float s = 0.f;
    if (threadIdx.x < head) s += __expf(lg[threadIdx.x]);
    if (threadIdx.x < V_ - tailstart) s += __expf(lg[tailstart + threadIdx.x]);

    const float4* lg4 = (const float4*)(lg + head);
    float s0 = 0.f, s1 = 0.f, s2 = 0.f, s3 = 0.f;
    for (int i = threadIdx.x; i < n4; i += 512) {
        const float4 v = lg4[i];
        s0 += __expf(v.x);
        s1 += __expf(v.y);
        s2 += __expf(v.z);
        s3 += __expf(v.w);
    }
    s += (s0 + s1) + (s2 + s3);

    #pragma unroll
    for (int off = 16; off > 0; off >>= 1)
        s += __shfl_xor_sync(0xFFFFFFFFu, s, off);

    __shared__ float warp_sums[16];
    const int wid = threadIdx.x >> 5;
    const int lid = threadIdx.x & 31;
    if (lid == 0) warp_sums[wid] = s;
    __syncthreads();

    if (wid == 0) {
        float t = (lid < 16) ? warp_sums[lid] : 0.f;
        #pragma unroll
        for (int off = 8; off > 0; off >>= 1)
            t += __shfl_xor_sync(0xFFFFFFFFu, t, off);
        if (lid == 0) g_escale[m * B_ + b] = w[m] / t;
    }
}

// ---------------------------------------------------------------------------
// 2) TMA bulk-reduce scatter.
// CTA = (16 j-columns, all 256 b) for one model m. Builds contiguous 1KB rows
// row[jj][b] = escale[m,b] * exp(logits[m][b][j0+jj]) in smem, then issues one
// cp.reduce.async.bulk (shared -> global, .add.f32) per j into g_outT[u].
// Elementwise adds execute atomically in L2 with no per-element SM issue cost.
// grid: (ceil(V/16), M), block 256.
// ---------------------------------------------------------------------------
__global__ void scatter_kernel(const float* __restrict__ l0,
                               const float* __restrict__ l1,
                               const float* __restrict__ l2,
                               const int*   __restrict__ m0,
                               const int*   __restrict__ m1,
                               const int*   __restrict__ m2) {
    __shared__ float s_scale[B_];
    __shared__ float s_stage[B_][TJ + 1];                    // [b][jj], padded
    __shared__ __align__(16) float s_row[TJ][B_];            // [jj][b], 1KB rows

    const int m  = blockIdx.y;
    const int j0 = blockIdx.x * TJ;
    const float* lg = (m == 0 ? l0 : (m == 1 ? l1 : l2));
    const int*   mp = (m == 0 ? m0 : (m == 1 ? m1 : m2));
    const int tid = threadIdx.x;

    s_scale[tid] = g_escale[m * B_ + tid];
    __syncthreads();

    // Phase 1: coalesced load + exp*scale -> s_stage[b][jj]
    #pragma unroll
    for (int i = 0; i < TJ; i++) {
        const int idx = i * 256 + tid;        // 0..4095
        const int bb  = idx >> 4;             // 0..255
        const int jj  = idx & (TJ - 1);
        const int j   = j0 + jj;
        float e = 0.f;
        if (j < V_) e = __expf(lg[(size_t)bb * V_ + j]) * s_scale[bb];
        s_stage[bb][jj] = e;
    }
    __syncthreads();

    // Phase 2: transpose to contiguous rows s_row[jj][0..255]
    #pragma unroll
    for (int i = 0; i < TJ; i++) {
        const int idx = i * 256 + tid;
        const int jj  = idx >> 8;             // 0..15
        const int bb  = idx & 255;
        s_row[jj][bb] = s_stage[bb][jj];
    }
    // make generic-proxy smem writes visible to the async (TMA) proxy
    asm volatile("fence.proxy.async.shared::cta;" ::: "memory");
    __syncthreads();

    // Phase 3: one bulk-reduce per j (lanes 0..TJ-1 of warp 0)
    if (tid < TJ) {
        const int j = j0 + tid;
        if (j < V_) {
            const int u = mp[j];
            float* dst = g_outT + (size_t)u * B_;
            const uint32_t saddr =
                (uint32_t)__cvta_generic_to_shared(&s_row[tid][0]);
            asm volatile(
                "cp.reduce.async.bulk.global.shared::cta.bulk_group.add.f32 "
                "[%0], [%1], %2;"
                :: "l"(dst), "r"(saddr), "r"(B_ * 4) : "memory");
            asm volatile("cp.async.bulk.commit_group;" ::: "memory");
            asm volatile("cp.async.bulk.wait_group 0;" ::: "memory");
        }
    }
}

// ---------------------------------------------------------------------------
// 3) transpose out_T[u][b] -> out[b][u], 32x32 tiles, and re-zero out_T
//    (restores the all-zeros invariant for the next graph replay).
// grid: (U/32, B/32), block (32, 8)
// ---------------------------------------------------------------------------
__global__ void transpose_kernel(float* __restrict__ out) {
    __shared__ float tile[32][33];
    const int u0 = blockIdx.x * 32;
    const int b0 = blockIdx.y * 32;
    const int tx = threadIdx.x;
    const int ty = threadIdx.y;

    #pragma unroll
    for (int k = 0; k < 4; k++) {
        const int u = u0 + ty + 8 * k;
        float* p = &g_outT[(size_t)u * B_ + b0 + tx];
        tile[ty + 8 * k][tx] = *p;
        *p = 0.f;                              // re-zero for next replay
    }
    __syncthreads();
    #pragma unroll
    for (int k = 0; k < 4; k++) {
        const int b = b0 + ty + 8 * k;
        out[(size_t)b * U_ + u0 + tx] = tile[tx][ty + 8 * k];
    }
}

// ---------------------------------------------------------------------------
// kernel_launch
// inputs: logits0, logits1, logits2, map0, map1, map2, weights
// ---------------------------------------------------------------------------
extern "C" void kernel_launch(void* const* d_in, const int* in_sizes, int n_in,
                              void* d_out, int out_size) {
    const float* l0 = (const float*)d_in[0];
    const float* l1 = (const float*)d_in[1];
    const float* l2 = (const float*)d_in[2];
    const int*   m0 = (const int*)d_in[3];
    const int*   m1 = (const int*)d_in[4];
    const int*   m2 = (const int*)d_in[5];
    const float* w  = (const float*)d_in[6];
    float* out = (float*)d_out;

    // 1) softmax denominators -> scales
    {
        dim3 grid(B_, M_);
        rowsum_kernel<<<grid, 512>>>(l0, l1, l2, w);
    }

    // 2) TMA bulk-reduce scatter into g_outT (zeroed invariant)
    {
        dim3 grid((V_ + TJ - 1) / TJ, M_);
        scatter_kernel<<<grid, 256>>>(l0, l1, l2, m0, m1, m2);
    }

    // 3) transpose to row-major output + re-zero accumulator
    {
        dim3 grid(U_ / 32, B_ / 32);
        dim3 block(32, 8);
        transpose_kernel<<<grid, block>>>(out);
    }
}